// round 3
// baseline (speedup 1.0000x reference)
#include <cuda_runtime.h>
#include <cuda_bf16.h>
#include <math.h>

// Problem constants
#define BATCH 4
#define SLEN  2048
#define EDIM  1024
#define NH    16
#define HDIM  64
#define QKVW  3072            // 3*E
#define HSTRIDE 192           // 3*HD per head inside qkv row

// ---------------------------------------------------------------------------
// Scratch (device globals: allocation is forbidden)
// ---------------------------------------------------------------------------
__device__ float g_qkv [(size_t)BATCH * SLEN * QKVW];   // [B*S, 3E]
__device__ float g_vals[(size_t)BATCH * SLEN * EDIM];   // [B*S, E]

// ---------------------------------------------------------------------------
// SIMT fp32 GEMM: C[M,N] = A[M,K] * B[K,N] + bias[N]
// BM=BN=128, BK=8, 256 threads, 8x8 microtile. M,N,K divisible by tiles.
// ---------------------------------------------------------------------------
__global__ __launch_bounds__(256)
void sgemm_bias(const float* __restrict__ A, const float* __restrict__ B,
                const float* __restrict__ bias, float* __restrict__ C,
                int M, int N, int K) {
    __shared__ float As[8][128];
    __shared__ float Bs[8][128];

    const int tid = threadIdx.x;
    const int tx  = tid & 15;          // 0..15  (col group)
    const int ty  = tid >> 4;          // 0..15  (row group)
    const int row0 = blockIdx.y * 128;
    const int col0 = blockIdx.x * 128;

    // A tile load: 128 rows x 8 cols -> 2 float4 per row, 1 float4 per thread
    const int aRow = tid >> 1;
    const int aCol = (tid & 1) << 2;
    // B tile load: 8 rows x 128 cols -> 32 float4 per row, 1 float4 per thread
    const int bRow = tid >> 5;
    const int bCol = (tid & 31) << 2;

    float acc[8][8];
#pragma unroll
    for (int i = 0; i < 8; i++)
#pragma unroll
        for (int j = 0; j < 8; j++) acc[i][j] = 0.f;

    for (int k0 = 0; k0 < K; k0 += 8) {
        float4 av = *(const float4*)&A[(size_t)(row0 + aRow) * K + k0 + aCol];
        As[aCol + 0][aRow] = av.x;
        As[aCol + 1][aRow] = av.y;
        As[aCol + 2][aRow] = av.z;
        As[aCol + 3][aRow] = av.w;
        float4 bv = *(const float4*)&B[(size_t)(k0 + bRow) * N + col0 + bCol];
        *(float4*)&Bs[bRow][bCol] = bv;
        __syncthreads();

#pragma unroll
        for (int kk = 0; kk < 8; kk++) {
            float ra[8], rb[8];
#pragma unroll
            for (int i = 0; i < 8; i++) ra[i] = As[kk][ty * 8 + i];
#pragma unroll
            for (int j = 0; j < 8; j++) rb[j] = Bs[kk][tx * 8 + j];
#pragma unroll
            for (int i = 0; i < 8; i++)
#pragma unroll
                for (int j = 0; j < 8; j++) acc[i][j] += ra[i] * rb[j];
        }
        __syncthreads();
    }

#pragma unroll
    for (int i = 0; i < 8; i++) {
        const int r = row0 + ty * 8 + i;
#pragma unroll
        for (int j = 0; j < 8; j += 4) {
            const int c = col0 + tx * 8 + j;
            float4 v;
            v.x = acc[i][j + 0] + bias[c + 0];
            v.y = acc[i][j + 1] + bias[c + 1];
            v.z = acc[i][j + 2] + bias[c + 2];
            v.w = acc[i][j + 3] + bias[c + 3];
            *(float4*)&C[(size_t)r * N + c] = v;
        }
    }
}

// ---------------------------------------------------------------------------
// Attention: block = (b, h, 64-row q-tile). Pass1 online softmax stats,
// pass2 recompute + write attn + accumulate P@V.
// Shared (dynamic): Qs[64][65], Ks[64][65], Ps[64][65], m[64], l[64]
// ---------------------------------------------------------------------------
#define TPAD 65
#define SM_FLOATS (3 * 64 * TPAD + 128)
#define SM_BYTES  (SM_FLOATS * 4)

__device__ __forceinline__ void load_tile64(float* dst, const float* __restrict__ qkv,
                                            int b, int s0, int h, int off, int tid) {
    const float* base = qkv + ((size_t)b * SLEN + s0) * QKVW + h * HSTRIDE + off;
#pragma unroll
    for (int i = 0; i < 4; i++) {
        int idx = tid + i * 256;
        int r   = idx >> 4;
        int c4  = (idx & 15) << 2;
        float4 v = *(const float4*)(base + (size_t)r * QKVW + c4);
        float* d = dst + r * TPAD + c4;
        d[0] = v.x; d[1] = v.y; d[2] = v.z; d[3] = v.w;
    }
}

__global__ __launch_bounds__(256)
void attn_kernel(const float* __restrict__ qkv,
                 float* __restrict__ attn_out,   // [B,H,S,S]
                 float* __restrict__ vals) {     // [B,S,E]
    extern __shared__ float sm[];
    float* Qs   = sm;
    float* Ks   = sm + 64 * TPAD;
    float* Ps   = sm + 2 * 64 * TPAD;
    float* mrow = sm + 3 * 64 * TPAD;
    float* lrow = mrow + 64;

    const int qt  = blockIdx.x;            // 0..31
    const int bh  = blockIdx.y;            // 0..63
    const int b   = bh >> 4;
    const int h   = bh & 15;
    const int tid = threadIdx.x;
    const int tx  = tid & 15;
    const int ty  = tid >> 4;
    const int q0  = qt * 64;

    load_tile64(Qs, qkv, b, q0, h, 0, tid);        // Q
    if (tid < 64) { mrow[tid] = -INFINITY; lrow[tid] = 0.f; }
    __syncthreads();

    const float scale = 0.125f;   // 1/sqrt(64)

    // ---------------- Pass 1: softmax stats ----------------
    for (int kt = 0; kt <= qt; kt++) {
        load_tile64(Ks, qkv, b, kt * 64, h, HDIM, tid);  // K
        __syncthreads();

        float s[4][4];
#pragma unroll
        for (int i = 0; i < 4; i++)
#pragma unroll
            for (int j = 0; j < 4; j++) s[i][j] = 0.f;
#pragma unroll 16
        for (int kk = 0; kk < 64; kk++) {
            float ra[4], rb[4];
#pragma unroll
            for (int i = 0; i < 4; i++) ra[i] = Qs[(ty * 4 + i) * TPAD + kk];
#pragma unroll
            for (int j = 0; j < 4; j++) rb[j] = Ks[(tx * 4 + j) * TPAD + kk];
#pragma unroll
            for (int i = 0; i < 4; i++)
#pragma unroll
                for (int j = 0; j < 4; j++) s[i][j] += ra[i] * rb[j];
        }
#pragma unroll
        for (int i = 0; i < 4; i++)
#pragma unroll
            for (int j = 0; j < 4; j++) {
                s[i][j] *= scale;
                if (kt == qt && (tx * 4 + j) > (ty * 4 + i)) s[i][j] = -9e15f;
            }

#pragma unroll
        for (int i = 0; i < 4; i++) {
            const int qr = ty * 4 + i;
            float tmax = fmaxf(fmaxf(s[i][0], s[i][1]), fmaxf(s[i][2], s[i][3]));
#pragma unroll
            for (int d = 1; d < 16; d <<= 1)
                tmax = fmaxf(tmax, __shfl_xor_sync(0xffffffffu, tmax, d));
            const float m_old = mrow[qr];
            const float m_new = fmaxf(m_old, tmax);
            float psum = 0.f;
#pragma unroll
            for (int j = 0; j < 4; j++) psum += __expf(s[i][j] - m_new);
#pragma unroll
            for (int d = 1; d < 16; d <<= 1)
                psum += __shfl_xor_sync(0xffffffffu, psum, d);
            if (tx == 0) {
                mrow[qr] = m_new;
                lrow[qr] = lrow[qr] * __expf(m_old - m_new) + psum;
            }
        }
        __syncthreads();
    }

    // ---------------- Pass 2: write attn + P@V ----------------
    float mf[4], linv[4];
#pragma unroll
    for (int i = 0; i < 4; i++) {
        mf[i]   = mrow[ty * 4 + i];
        linv[i] = 1.f / lrow[ty * 4 + i];
    }
    float o[4][4];
#pragma unroll
    for (int i = 0; i < 4; i++)
#pragma unroll
        for (int j = 0; j < 4; j++) o[i][j] = 0.f;

    float* attn_base = attn_out + ((size_t)bh * SLEN + q0) * SLEN;

    for (int kt = 0; kt < SLEN / 64; kt++) {
        const int k0 = kt * 64;
        if (kt <= qt) {
            load_tile64(Ks, qkv, b, k0, h, HDIM, tid);   // K again
            __syncthreads();

            float s[4][4];
#pragma unroll
            for (int i = 0; i < 4; i++)
#pragma unroll
                for (int j = 0; j < 4; j++) s[i][j] = 0.f;
#pragma unroll 16
            for (int kk = 0; kk < 64; kk++) {
                float ra[4], rb[4];
#pragma unroll
                for (int i = 0; i < 4; i++) ra[i] = Qs[(ty * 4 + i) * TPAD + kk];
#pragma unroll
                for (int j = 0; j < 4; j++) rb[j] = Ks[(tx * 4 + j) * TPAD + kk];
#pragma unroll
                for (int i = 0; i < 4; i++)
#pragma unroll
                    for (int j = 0; j < 4; j++) s[i][j] += ra[i] * rb[j];
            }
#pragma unroll
            for (int i = 0; i < 4; i++) {
                float4 pv;
                float p[4];
#pragma unroll
                for (int j = 0; j < 4; j++) {
                    float sv = s[i][j] * scale;
                    if (kt == qt && (tx * 4 + j) > (ty * 4 + i)) sv = -9e15f;
                    p[j] = __expf(sv - mf[i]) * linv[i];
                    Ps[(ty * 4 + i) * TPAD + tx * 4 + j] = p[j];
                }
                pv.x = p[0]; pv.y = p[1]; pv.z = p[2]; pv.w = p[3];
                *(float4*)(attn_base + (size_t)(ty * 4 + i) * SLEN + k0 + tx * 4) = pv;
            }
            __syncthreads();                             // Ps done, Ks reads done

            load_tile64(Ks, qkv, b, k0, h, 2 * HDIM, tid); // V
            __syncthreads();

#pragma unroll 16
            for (int kk = 0; kk < 64; kk++) {
                float pa[4], vb[4];
#pragma unroll
                for (int i = 0; i < 4; i++) pa[i] = Ps[(ty * 4 + i) * TPAD + kk];
#pragma unroll
                for (int j = 0; j < 4; j++) vb[j] = Ks[kk * TPAD + tx * 4 + j];
#pragma unroll
                for (int i = 0; i < 4; i++)
#pragma unroll
                    for (int j = 0; j < 4; j++) o[i][j] += pa[i] * vb[j];
            }
            __syncthreads();                             // before next K load
        } else {
            // Upper triangle of attn must be exactly zero (d_out is poisoned)
            const float4 z = make_float4(0.f, 0.f, 0.f, 0.f);
#pragma unroll
            for (int i = 0; i < 4; i++)
                *(float4*)(attn_base + (size_t)(ty * 4 + i) * SLEN + k0 + tx * 4) = z;
        }
    }

    // write O tile into vals[b, q, h*64 + d]
#pragma unroll
    for (int i = 0; i < 4; i++) {
        const int r = q0 + ty * 4 + i;
        float4 v;
        v.x = o[i][0]; v.y = o[i][1]; v.z = o[i][2]; v.w = o[i][3];
        *(float4*)&vals[((size_t)b * SLEN + r) * EDIM + h * HDIM + tx * 4] = v;
    }
}

// ---------------------------------------------------------------------------
// Launch
// ---------------------------------------------------------------------------
extern "C" void kernel_launch(void* const* d_in, const int* in_sizes, int n_in,
                              void* d_out, int out_size) {
    const float* x     = (const float*)d_in[0];   // [B,S,E]
    const float* w_qkv = (const float*)d_in[1];   // [E,3E]
    const float* b_qkv = (const float*)d_in[2];   // [3E]
    const float* w_o   = (const float*)d_in[3];   // [E,E]
    const float* b_o   = (const float*)d_in[4];   // [E]
    // d_in[5] = mask (causal tril) -- structure known, not read

    float* out  = (float*)d_out;
    float* o_out    = out;                                        // [B,S,E]
    float* attn_out = out + (size_t)BATCH * SLEN * EDIM;          // [B,H,S,S]

    float* qkv  = nullptr;
    float* vals = nullptr;
    cudaGetSymbolAddress((void**)&qkv,  g_qkv);
    cudaGetSymbolAddress((void**)&vals, g_vals);

    cudaFuncSetAttribute(attn_kernel, cudaFuncAttributeMaxDynamicSharedMemorySize, SM_BYTES);

    const int M = BATCH * SLEN;  // 8192

    // 1) QKV projection: [8192,1024] x [1024,3072]
    {
        dim3 grid(QKVW / 128, M / 128);
        sgemm_bias<<<grid, 256>>>(x, w_qkv, b_qkv, qkv, M, QKVW, EDIM);
    }
    // 2) attention (writes attn_out and vals)
    {
        dim3 grid(SLEN / 64, BATCH * NH);
        attn_kernel<<<grid, 256, SM_BYTES>>>(qkv, attn_out, vals);
    }
    // 3) output projection: [8192,1024] x [1024,1024]
    {
        dim3 grid(EDIM / 128, M / 128);
        sgemm_bias<<<grid, 256>>>(vals, w_o, b_o, o_out, M, EDIM, EDIM);
    }
}